// round 4
// baseline (speedup 1.0000x reference)
#include <cuda_runtime.h>
#include <cstdint>

#define TOKENS  4096
#define DMODEL  512
#define VOCAB   128000
#define BM      64
#define BN      128
#define BK      64            /* fp8 elems per k-chunk = 64 bytes */
#define NSPLITS 37
#define NTILES_N (VOCAB / BN)   /* 1000 */
#define MTILES   (TOKENS / BM)  /* 64   */

// smem strides (bytes), padded for conflict-free ldmatrix
#define ASTRIDE 528   /* 512 + 16 ; 528/16 mod 8 = 1 -> distinct granules */
#define BSTRIDE 80    /* 64 + 16  ; 80/16  mod 8 = 5 -> distinct granules */
#define BSTAGE  (128 * BSTRIDE)          /* 10240 */
#define A_BYTES (BM * ASTRIDE)           /* 33792 */
#define SMEM_TOTAL (A_BYTES + 4 * BSTAGE + BM * 4 * 4)  /* 75776 */

// scales: x*16, W*1024 -> logits scaled 16384x ; exp(l) = 2^(l_s * log2e/16384)
#define SW_X 16.0f
#define SW_W 1024.0f
#define EPI_SCALE 8.805453862847030e-5f   /* log2(e)/16384 */

// ---------------- scratch ----------------
__device__ __align__(16) uint8_t g_X8[TOKENS * DMODEL];
__device__ __align__(16) uint8_t g_W8[(size_t)VOCAB * DMODEL];
__device__ float g_ts[TOKENS];
__device__ float g_sum[NSPLITS * TOKENS];

// ---------------- ptx helpers ----------------
__device__ __forceinline__ float ex2f(float x) {
    float r; asm("ex2.approx.f32 %0, %1;" : "=f"(r) : "f"(x)); return r;
}
__device__ __forceinline__ uint16_t cvt2_e4m3(float lo, float hi) {
    uint16_t r;
    asm("cvt.rn.satfinite.e4m3x2.f32 %0, %1, %2;" : "=h"(r) : "f"(hi), "f"(lo));
    return r;
}
__device__ __forceinline__ void mma_f8(float d[4], const uint32_t a[4],
                                       uint32_t b0, uint32_t b1) {
    asm volatile(
        "mma.sync.aligned.m16n8k32.row.col.f32.e4m3.e4m3.f32 "
        "{%0,%1,%2,%3},{%4,%5,%6,%7},{%8,%9},{%0,%1,%2,%3};"
        : "+f"(d[0]), "+f"(d[1]), "+f"(d[2]), "+f"(d[3])
        : "r"(a[0]), "r"(a[1]), "r"(a[2]), "r"(a[3]), "r"(b0), "r"(b1));
}
#define LDMX4(r0, r1, r2, r3, addr)                                          \
    asm volatile("ldmatrix.sync.aligned.m8n8.x4.shared.b16 {%0,%1,%2,%3},[%4];" \
                 : "=r"(r0), "=r"(r1), "=r"(r2), "=r"(r3) : "r"(addr))

// ---------------- fp8 conversion ----------------
__global__ void convert_w8(const float* __restrict__ src) {
    size_t i = ((size_t)blockIdx.x * blockDim.x + threadIdx.x) * 16;
    const float4* s = reinterpret_cast<const float4*>(src + i);
    float4 f0 = s[0], f1 = s[1], f2 = s[2], f3 = s[3];
    uint32_t u0 = (uint32_t)cvt2_e4m3(f0.x * SW_W, f0.y * SW_W) |
                  ((uint32_t)cvt2_e4m3(f0.z * SW_W, f0.w * SW_W) << 16);
    uint32_t u1 = (uint32_t)cvt2_e4m3(f1.x * SW_W, f1.y * SW_W) |
                  ((uint32_t)cvt2_e4m3(f1.z * SW_W, f1.w * SW_W) << 16);
    uint32_t u2 = (uint32_t)cvt2_e4m3(f2.x * SW_W, f2.y * SW_W) |
                  ((uint32_t)cvt2_e4m3(f2.z * SW_W, f2.w * SW_W) << 16);
    uint32_t u3 = (uint32_t)cvt2_e4m3(f3.x * SW_W, f3.y * SW_W) |
                  ((uint32_t)cvt2_e4m3(f3.z * SW_W, f3.w * SW_W) << 16);
    *reinterpret_cast<uint4*>(g_W8 + i) = make_uint4(u0, u1, u2, u3);
}
__global__ void convert_x8(const float* __restrict__ src) {
    size_t i = ((size_t)blockIdx.x * blockDim.x + threadIdx.x) * 16;
    const float4* s = reinterpret_cast<const float4*>(src + i);
    float4 f0 = s[0], f1 = s[1], f2 = s[2], f3 = s[3];
    uint32_t u0 = (uint32_t)cvt2_e4m3(f0.x * SW_X, f0.y * SW_X) |
                  ((uint32_t)cvt2_e4m3(f0.z * SW_X, f0.w * SW_X) << 16);
    uint32_t u1 = (uint32_t)cvt2_e4m3(f1.x * SW_X, f1.y * SW_X) |
                  ((uint32_t)cvt2_e4m3(f1.z * SW_X, f1.w * SW_X) << 16);
    uint32_t u2 = (uint32_t)cvt2_e4m3(f2.x * SW_X, f2.y * SW_X) |
                  ((uint32_t)cvt2_e4m3(f2.z * SW_X, f2.w * SW_X) << 16);
    uint32_t u3 = (uint32_t)cvt2_e4m3(f3.x * SW_X, f3.y * SW_X) |
                  ((uint32_t)cvt2_e4m3(f3.z * SW_X, f3.w * SW_X) << 16);
    *reinterpret_cast<uint4*>(g_X8 + i) = make_uint4(u0, u1, u2, u3);
}

// ---------------- target score (exact fp32) ----------------
__global__ void target_score_kernel(const float* __restrict__ x,
                                    const float* __restrict__ w,
                                    const int* __restrict__ target) {
    int t = blockIdx.x * 8 + (threadIdx.x >> 5);
    int lane = threadIdx.x & 31;
    if (t >= TOKENS) return;
    int tgt = target[t];
    const float4* xr = reinterpret_cast<const float4*>(x + (size_t)t * DMODEL);
    const float4* wr = reinterpret_cast<const float4*>(w + (size_t)tgt * DMODEL);
    float s = 0.0f;
    #pragma unroll
    for (int i = lane; i < DMODEL / 4; i += 32) {
        float4 a = xr[i]; float4 b = wr[i];
        s += a.x * b.x + a.y * b.y + a.z * b.z + a.w * b.w;
    }
    #pragma unroll
    for (int o = 16; o; o >>= 1) s += __shfl_xor_sync(0xffffffffu, s, o);
    if (lane == 0) g_ts[t] = s;
}

// B-chunk producer: one (n-tile, k-chunk) = 128 rows x 64 B via cp.async
__device__ __forceinline__ void issue_b(int q, int tid, int split, uint32_t Bs_u) {
    int nt = split + NSPLITS * (q >> 3);
    int kc = q & 7;
    const uint8_t* src = g_W8 + (size_t)nt * (BN * DMODEL) + kc * BK;
    uint32_t dst = Bs_u + (uint32_t)((q & 3) * BSTAGE);
    #pragma unroll
    for (int i = 0; i < 2; ++i) {
        int ch = tid + i * 256;          // 512 chunks of 16B, 4 per row
        int row = ch >> 2, c16 = ch & 3;
        uint32_t sa = dst + (uint32_t)(row * BSTRIDE + c16 * 16);
        const void* g = (const void*)(src + (size_t)row * DMODEL + c16 * 16);
        asm volatile("cp.async.cg.shared.global [%0], [%1], 16;\n" :: "r"(sa), "l"(g));
    }
    asm volatile("cp.async.commit_group;\n" ::: "memory");
}

// ---------------- main CE partial kernel (fp8 mma.sync, 2 CTAs/SM) ----------------
__global__ void __launch_bounds__(256, 2) ce8_kernel() {
    extern __shared__ char smem[];
    const int tid = threadIdx.x;
    const int lane = tid & 31;
    const int wid = tid >> 5;
    const int warpm = wid >> 2;   // 0..1  (32 rows each)
    const int warpn = wid & 3;    // 0..3  (32 cols each)
    const int tile_m = blockIdx.x;
    const int split  = blockIdx.y;

    float* red = reinterpret_cast<float*>(smem + A_BYTES + 4 * BSTAGE);
    const uint32_t As_u = (uint32_t)__cvta_generic_to_shared(smem);
    const uint32_t Bs_u = As_u + A_BYTES;

    // ---- A tile: 64 x 512 fp8, loaded once ----
    {
        const uint8_t* src = g_X8 + (size_t)tile_m * (BM * DMODEL);
        #pragma unroll
        for (int it = 0; it < 8; ++it) {
            int ch = tid + it * 256;      // 2048 chunks of 16B, 32 per row
            int row = ch >> 5, c16 = ch & 31;
            uint32_t sa = As_u + (uint32_t)(row * ASTRIDE + c16 * 16);
            const void* g = (const void*)(src + (size_t)row * DMODEL + c16 * 16);
            asm volatile("cp.async.cg.shared.global [%0], [%1], 16;\n" :: "r"(sa), "l"(g));
        }
        asm volatile("cp.async.commit_group;\n" ::: "memory");
    }

    const int ntile_cnt = (NTILES_N - 1 - split) / NSPLITS + 1;  // 27 or 28
    const int Q = ntile_cnt * 8;

    issue_b(0, tid, split, Bs_u);
    issue_b(1, tid, split, Bs_u);
    issue_b(2, tid, split, Bs_u);

    float rs[4];
    #pragma unroll
    for (int i = 0; i < 4; ++i) rs[i] = 0.0f;

    float acc[2][4][4];

    // fragment addressing (byte offsets; fp8 elements are 1 byte)
    const int a_row = warpm * 32 + (lane & 15);
    const int a_csel = ((lane >> 4) & 1) * 16;
    const int b_row = warpn * 32 + ((lane >> 4) & 1) * 8 + (lane & 7);
    const int b_csel = ((lane >> 3) & 1) * 16;

    for (int q = 0; q < Q; ++q) {
        int rem = Q - 1 - q;
        if (rem >= 2)      asm volatile("cp.async.wait_group 2;\n" ::: "memory");
        else if (rem == 1) asm volatile("cp.async.wait_group 1;\n" ::: "memory");
        else               asm volatile("cp.async.wait_group 0;\n" ::: "memory");
        __syncthreads();

        int kc = q & 7;
        if (kc == 0) {
            #pragma unroll
            for (int mt = 0; mt < 2; ++mt)
                #pragma unroll
                for (int nt = 0; nt < 4; ++nt)
                    #pragma unroll
                    for (int j = 0; j < 4; ++j) acc[mt][nt][j] = 0.0f;
        }

        uint32_t bbase = Bs_u + (uint32_t)((q & 3) * BSTAGE);
        #pragma unroll
        for (int ks = 0; ks < 2; ++ks) {      // two k32 steps per 64B chunk
            int kbyte = kc * BK + ks * 32;
            uint32_t a[2][4];
            #pragma unroll
            for (int mt = 0; mt < 2; ++mt) {
                uint32_t sa = As_u + (uint32_t)((a_row + mt * 16) * ASTRIDE + kbyte + a_csel);
                LDMX4(a[mt][0], a[mt][1], a[mt][2], a[mt][3], sa);
            }
            uint32_t b[2][4];
            #pragma unroll
            for (int np = 0; np < 2; ++np) {
                uint32_t sb = bbase + (uint32_t)((b_row + np * 16) * BSTRIDE + ks * 32 + b_csel);
                LDMX4(b[np][0], b[np][1], b[np][2], b[np][3], sb);
            }
            #pragma unroll
            for (int mt = 0; mt < 2; ++mt)
                #pragma unroll
                for (int np = 0; np < 2; ++np) {
                    mma_f8(acc[mt][np * 2 + 0], a[mt], b[np][0], b[np][1]);
                    mma_f8(acc[mt][np * 2 + 1], a[mt], b[np][2], b[np][3]);
                }
        }

        if (kc == 7) {  // tile complete: fold logits into running exp-sums
            #pragma unroll
            for (int mt = 0; mt < 2; ++mt) {
                float s0 = 0.0f, s1 = 0.0f;
                #pragma unroll
                for (int nt = 0; nt < 4; ++nt) {
                    s0 += ex2f(acc[mt][nt][0] * EPI_SCALE) + ex2f(acc[mt][nt][1] * EPI_SCALE);
                    s1 += ex2f(acc[mt][nt][2] * EPI_SCALE) + ex2f(acc[mt][nt][3] * EPI_SCALE);
                }
                rs[mt * 2 + 0] += s0;
                rs[mt * 2 + 1] += s1;
            }
        }

        if (q + 3 < Q) issue_b(q + 3, tid, split, Bs_u);
    }

    // ---- reduce: quad (n within warp) -> smem (across warpn) ----
    #pragma unroll
    for (int i = 0; i < 4; ++i) {
        rs[i] += __shfl_xor_sync(0xffffffffu, rs[i], 1);
        rs[i] += __shfl_xor_sync(0xffffffffu, rs[i], 2);
    }
    __syncthreads();
    if ((lane & 3) == 0) {
        int g = lane >> 2;
        #pragma unroll
        for (int mt = 0; mt < 2; ++mt)
            #pragma unroll
            for (int rh = 0; rh < 2; ++rh) {
                int row = warpm * 32 + mt * 16 + rh * 8 + g;
                red[row * 4 + warpn] = rs[mt * 2 + rh];
            }
    }
    __syncthreads();
    if (tid < BM) {
        float s = red[tid * 4 + 0] + red[tid * 4 + 1] + red[tid * 4 + 2] + red[tid * 4 + 3];
        g_sum[split * TOKENS + tile_m * BM + tid] = s;
    }
}

// ---------------- final loss reduce ----------------
__global__ void loss_kernel(float* __restrict__ out) {
    __shared__ float sm[256];
    float acc = 0.0f;
    for (int t = threadIdx.x; t < TOKENS; t += 256) {
        float S = 0.0f;
        #pragma unroll
        for (int s = 0; s < NSPLITS; ++s) S += g_sum[s * TOKENS + t];
        acc += logf(S) - g_ts[t];
    }
    sm[threadIdx.x] = acc;
    __syncthreads();
    #pragma unroll
    for (int o = 128; o; o >>= 1) {
        if (threadIdx.x < o) sm[threadIdx.x] += sm[threadIdx.x + o];
        __syncthreads();
    }
    if (threadIdx.x == 0) out[0] = sm[0];
}

// ---------------- launch ----------------
extern "C" void kernel_launch(void* const* d_in, const int* in_sizes, int n_in,
                              void* d_out, int out_size) {
    const float* x = (const float*)d_in[0];
    const float* w = (const float*)d_in[1];
    const int* target = (const int*)d_in[2];
    float* out = (float*)d_out;
    (void)in_sizes; (void)n_in; (void)out_size;

    cudaFuncSetAttribute(ce8_kernel, cudaFuncAttributeMaxDynamicSharedMemorySize,
                         SMEM_TOTAL);

    convert_w8<<<16000, 256>>>(w);                    // 16000*256*16 = 65,536,000
    convert_x8<<<512, 256>>>(x);                      // 512*256*16  =  2,097,152
    target_score_kernel<<<TOKENS / 8, 256>>>(x, w, target);
    ce8_kernel<<<dim3(MTILES, NSPLITS), 256, SMEM_TOTAL>>>();
    loss_kernel<<<1, 256>>>(out);
}

// round 5
// speedup vs baseline: 1.0155x; 1.0155x over previous
#include <cuda_runtime.h>
#include <cstdint>

#define TOKENS  4096
#define DMODEL  512
#define VOCAB   128000
#define BM      128
#define BN      128
#define BK      128           /* fp8 elems per k-chunk = 128 bytes */
#define NSPLITS 37
#define NTILES_N (VOCAB / BN)   /* 1000 */
#define MTILES   (TOKENS / BM)  /* 32   */

// smem strides (bytes), padded for conflict-free ldmatrix
#define ASTRIDE 528   /* 512 + 16 */
#define BSTRIDE 144   /* 128 + 16 */
#define BSTAGE  (128 * BSTRIDE)          /* 18432 */
#define A_BYTES (BM * ASTRIDE)           /* 67584 */
#define SMEM_TOTAL (A_BYTES + 4 * BSTAGE)  /* 141312 */

// scales: x*16, W*1024 -> logits scaled 16384x ; exp(l) = 2^(l_s * log2e/16384)
#define SW_X 16.0f
#define SW_W 1024.0f
#define EPI_SCALE 8.805453862847030e-5f   /* log2(e)/16384 */

// ---------------- scratch ----------------
__device__ __align__(16) uint8_t g_X8[TOKENS * DMODEL];
__device__ __align__(16) uint8_t g_W8[(size_t)VOCAB * DMODEL];
__device__ float g_ts[TOKENS];
__device__ float g_sum[NSPLITS * TOKENS];

// ---------------- ptx helpers ----------------
__device__ __forceinline__ float ex2f(float x) {
    float r; asm("ex2.approx.f32 %0, %1;" : "=f"(r) : "f"(x)); return r;
}
__device__ __forceinline__ uint16_t cvt2_e4m3(float lo, float hi) {
    uint16_t r;
    asm("cvt.rn.satfinite.e4m3x2.f32 %0, %1, %2;" : "=h"(r) : "f"(hi), "f"(lo));
    return r;
}
__device__ __forceinline__ void mma_f8(float d[4], const uint32_t a[4],
                                       uint32_t b0, uint32_t b1) {
    asm volatile(
        "mma.sync.aligned.m16n8k32.row.col.f32.e4m3.e4m3.f32 "
        "{%0,%1,%2,%3},{%4,%5,%6,%7},{%8,%9},{%0,%1,%2,%3};"
        : "+f"(d[0]), "+f"(d[1]), "+f"(d[2]), "+f"(d[3])
        : "r"(a[0]), "r"(a[1]), "r"(a[2]), "r"(a[3]), "r"(b0), "r"(b1));
}
#define LDMX4(r0, r1, r2, r3, addr)                                          \
    asm volatile("ldmatrix.sync.aligned.m8n8.x4.shared.b16 {%0,%1,%2,%3},[%4];" \
                 : "=r"(r0), "=r"(r1), "=r"(r2), "=r"(r3) : "r"(addr))

// ---------------- fp8 conversion ----------------
__global__ void convert_w8(const float* __restrict__ src) {
    size_t i = ((size_t)blockIdx.x * blockDim.x + threadIdx.x) * 16;
    const float4* s = reinterpret_cast<const float4*>(src + i);
    float4 f0 = s[0], f1 = s[1], f2 = s[2], f3 = s[3];
    uint32_t u0 = (uint32_t)cvt2_e4m3(f0.x * SW_W, f0.y * SW_W) |
                  ((uint32_t)cvt2_e4m3(f0.z * SW_W, f0.w * SW_W) << 16);
    uint32_t u1 = (uint32_t)cvt2_e4m3(f1.x * SW_W, f1.y * SW_W) |
                  ((uint32_t)cvt2_e4m3(f1.z * SW_W, f1.w * SW_W) << 16);
    uint32_t u2 = (uint32_t)cvt2_e4m3(f2.x * SW_W, f2.y * SW_W) |
                  ((uint32_t)cvt2_e4m3(f2.z * SW_W, f2.w * SW_W) << 16);
    uint32_t u3 = (uint32_t)cvt2_e4m3(f3.x * SW_W, f3.y * SW_W) |
                  ((uint32_t)cvt2_e4m3(f3.z * SW_W, f3.w * SW_W) << 16);
    *reinterpret_cast<uint4*>(g_W8 + i) = make_uint4(u0, u1, u2, u3);
}
__global__ void convert_x8(const float* __restrict__ src) {
    size_t i = ((size_t)blockIdx.x * blockDim.x + threadIdx.x) * 16;
    const float4* s = reinterpret_cast<const float4*>(src + i);
    float4 f0 = s[0], f1 = s[1], f2 = s[2], f3 = s[3];
    uint32_t u0 = (uint32_t)cvt2_e4m3(f0.x * SW_X, f0.y * SW_X) |
                  ((uint32_t)cvt2_e4m3(f0.z * SW_X, f0.w * SW_X) << 16);
    uint32_t u1 = (uint32_t)cvt2_e4m3(f1.x * SW_X, f1.y * SW_X) |
                  ((uint32_t)cvt2_e4m3(f1.z * SW_X, f1.w * SW_X) << 16);
    uint32_t u2 = (uint32_t)cvt2_e4m3(f2.x * SW_X, f2.y * SW_X) |
                  ((uint32_t)cvt2_e4m3(f2.z * SW_X, f2.w * SW_X) << 16);
    uint32_t u3 = (uint32_t)cvt2_e4m3(f3.x * SW_X, f3.y * SW_X) |
                  ((uint32_t)cvt2_e4m3(f3.z * SW_X, f3.w * SW_X) << 16);
    *reinterpret_cast<uint4*>(g_X8 + i) = make_uint4(u0, u1, u2, u3);
}

// ---------------- target score (exact fp32) ----------------
__global__ void target_score_kernel(const float* __restrict__ x,
                                    const float* __restrict__ w,
                                    const int* __restrict__ target) {
    int t = blockIdx.x * 8 + (threadIdx.x >> 5);
    int lane = threadIdx.x & 31;
    if (t >= TOKENS) return;
    int tgt = target[t];
    const float4* xr = reinterpret_cast<const float4*>(x + (size_t)t * DMODEL);
    const float4* wr = reinterpret_cast<const float4*>(w + (size_t)tgt * DMODEL);
    float s = 0.0f;
    #pragma unroll
    for (int i = lane; i < DMODEL / 4; i += 32) {
        float4 a = xr[i]; float4 b = wr[i];
        s += a.x * b.x + a.y * b.y + a.z * b.z + a.w * b.w;
    }
    #pragma unroll
    for (int o = 16; o; o >>= 1) s += __shfl_xor_sync(0xffffffffu, s, o);
    if (lane == 0) g_ts[t] = s;
}

// B-chunk producer: one (n-tile, k-chunk) = 128 rows x 128 B via cp.async
__device__ __forceinline__ void issue_b(int q, int tid, int split, uint32_t Bs_u) {
    int nt = split + NSPLITS * (q >> 2);
    int kc = q & 3;
    const uint8_t* src = g_W8 + (size_t)nt * (BN * DMODEL) + kc * BK;
    uint32_t dst = Bs_u + (uint32_t)((q & 3) * BSTAGE);
    #pragma unroll
    for (int i = 0; i < 4; ++i) {
        int ch = tid + i * 256;          // 1024 chunks of 16B, 8 per row
        int row = ch >> 3, c16 = ch & 7;
        uint32_t sa = dst + (uint32_t)(row * BSTRIDE + c16 * 16);
        const void* g = (const void*)(src + (size_t)row * DMODEL + c16 * 16);
        asm volatile("cp.async.cg.shared.global [%0], [%1], 16;\n" :: "r"(sa), "l"(g));
    }
    asm volatile("cp.async.commit_group;\n" ::: "memory");
}

// ---------------- main CE partial kernel (fp8 mma.sync, 8x1 warp layout) ----------------
__global__ void __launch_bounds__(256, 1) ce8_kernel() {
    extern __shared__ char smem[];
    const int tid = threadIdx.x;
    const int lane = tid & 31;
    const int wid = tid >> 5;            // warp owns m-rows [wid*16, wid*16+16)
    const int tile_m = blockIdx.x;
    const int split  = blockIdx.y;

    const uint32_t As_u = (uint32_t)__cvta_generic_to_shared(smem);
    const uint32_t Bs_u = As_u + A_BYTES;

    // ---- A tile: 128 x 512 fp8, loaded once ----
    {
        const uint8_t* src = g_X8 + (size_t)tile_m * (BM * DMODEL);
        #pragma unroll
        for (int it = 0; it < 16; ++it) {
            int ch = tid + it * 256;      // 4096 chunks of 16B, 32 per row
            int row = ch >> 5, c16 = ch & 31;
            uint32_t sa = As_u + (uint32_t)(row * ASTRIDE + c16 * 16);
            const void* g = (const void*)(src + (size_t)row * DMODEL + c16 * 16);
            asm volatile("cp.async.cg.shared.global [%0], [%1], 16;\n" :: "r"(sa), "l"(g));
        }
        asm volatile("cp.async.commit_group;\n" ::: "memory");
    }

    const int ntile_cnt = (NTILES_N - 1 - split) / NSPLITS + 1;  // 27 or 28
    const int Q = ntile_cnt * 4;

    issue_b(0, tid, split, Bs_u);
    issue_b(1, tid, split, Bs_u);
    issue_b(2, tid, split, Bs_u);

    float rs0 = 0.0f, rs1 = 0.0f;
    float acc[16][4];                    // 16 n8-groups x 4 regs (m16 x n128)

    // ldmatrix addressing (byte offsets; fp8 = 1 byte)
    const uint32_t a_base = As_u +
        (uint32_t)((wid * 16 + (lane & 15)) * ASTRIDE + ((lane >> 4) & 1) * 16);
    const uint32_t b_lane_off =
        (uint32_t)((((lane >> 4) & 1) * 8 + (lane & 7)) * BSTRIDE + ((lane >> 3) & 1) * 16);

    for (int q = 0; q < Q; ++q) {
        int rem = Q - 1 - q;
        if (rem >= 2)      asm volatile("cp.async.wait_group 2;\n" ::: "memory");
        else if (rem == 1) asm volatile("cp.async.wait_group 1;\n" ::: "memory");
        else               asm volatile("cp.async.wait_group 0;\n" ::: "memory");
        __syncthreads();

        int kc = q & 3;
        if (kc == 0) {
            #pragma unroll
            for (int g = 0; g < 16; ++g)
                #pragma unroll
                for (int j = 0; j < 4; ++j) acc[g][j] = 0.0f;
        }

        const uint32_t bbase = Bs_u + (uint32_t)((q & 3) * BSTAGE) + b_lane_off;
        #pragma unroll
        for (int ks = 0; ks < 4; ++ks) {      // four k32 steps per 128B chunk
            uint32_t a[4];
            LDMX4(a[0], a[1], a[2], a[3], a_base + (uint32_t)(kc * BK + ks * 32));
            #pragma unroll
            for (int nq = 0; nq < 4; ++nq) {  // 4 x (n32 k32)
                uint32_t b0, b1, b2, b3;
                LDMX4(b0, b1, b2, b3, bbase + (uint32_t)(nq * 32 * BSTRIDE + ks * 32));
                mma_f8(acc[nq * 4 + 0], a, b0, b1);
                mma_f8(acc[nq * 4 + 1], a, b2, b3);
                // second n16 half of this n32 quadrant
                uint32_t c0, c1, c2, c3;
                LDMX4(c0, c1, c2, c3, bbase + (uint32_t)((nq * 32 + 16) * BSTRIDE + ks * 32));
                mma_f8(acc[nq * 4 + 2], a, c0, c1);
                mma_f8(acc[nq * 4 + 3], a, c2, c3);
            }
        }

        if (kc == 3) {  // tile complete: fold logits into running exp-sums
            #pragma unroll
            for (int g = 0; g < 16; ++g) {
                rs0 += ex2f(acc[g][0] * EPI_SCALE) + ex2f(acc[g][1] * EPI_SCALE);
                rs1 += ex2f(acc[g][2] * EPI_SCALE) + ex2f(acc[g][3] * EPI_SCALE);
            }
        }

        if (q + 3 < Q) issue_b(q + 3, tid, split, Bs_u);
    }

    // ---- warp-private reduce: sum over the 4 lanes of each quad (n direction) ----
    rs0 += __shfl_xor_sync(0xffffffffu, rs0, 1);
    rs0 += __shfl_xor_sync(0xffffffffu, rs0, 2);
    rs1 += __shfl_xor_sync(0xffffffffu, rs1, 1);
    rs1 += __shfl_xor_sync(0xffffffffu, rs1, 2);
    if ((lane & 3) == 0) {
        int row = tile_m * BM + wid * 16 + (lane >> 2);
        g_sum[split * TOKENS + row] = rs0;
        g_sum[split * TOKENS + row + 8] = rs1;
    }
}

// ---------------- final loss reduce ----------------
__global__ void loss_kernel(float* __restrict__ out) {
    __shared__ float sm[256];
    float acc = 0.0f;
    for (int t = threadIdx.x; t < TOKENS; t += 256) {
        float S = 0.0f;
        #pragma unroll
        for (int s = 0; s < NSPLITS; ++s) S += g_sum[s * TOKENS + t];
        acc += logf(S) - g_ts[t];
    }
    sm[threadIdx.x] = acc;
    __syncthreads();
    #pragma unroll
    for (int o = 128; o; o >>= 1) {
        if (threadIdx.x < o) sm[threadIdx.x] += sm[threadIdx.x + o];
        __syncthreads();
    }
    if (threadIdx.x == 0) out[0] = sm[0];
}

// ---------------- launch ----------------
extern "C" void kernel_launch(void* const* d_in, const int* in_sizes, int n_in,
                              void* d_out, int out_size) {
    const float* x = (const float*)d_in[0];
    const float* w = (const float*)d_in[1];
    const int* target = (const int*)d_in[2];
    float* out = (float*)d_out;
    (void)in_sizes; (void)n_in; (void)out_size;

    cudaFuncSetAttribute(ce8_kernel, cudaFuncAttributeMaxDynamicSharedMemorySize,
                         SMEM_TOTAL);

    convert_w8<<<16000, 256>>>(w);                    // 16000*256*16 = 65,536,000
    convert_x8<<<512, 256>>>(x);                      // 512*256*16  =  2,097,152
    target_score_kernel<<<TOKENS / 8, 256>>>(x, w, target);
    ce8_kernel<<<dim3(MTILES, NSPLITS), 256, SMEM_TOTAL>>>();
    loss_kernel<<<1, 256>>>(out);
}

// round 6
// speedup vs baseline: 1.0752x; 1.0588x over previous
#include <cuda_runtime.h>
#include <cstdint>

#define TOKENS  4096
#define DMODEL  512
#define VOCAB   128000
#define BM      256
#define BN      128
#define BK      128           /* fp8 elems per k-chunk = 128 bytes */
#define NSPLITS 37
#define NTILES_N (VOCAB / BN)   /* 1000 */
#define MTILES   (TOKENS / BM)  /* 16   */

// smem strides (bytes), padded for conflict-free ldmatrix
#define ASTRIDE 528   /* 512 + 16 */
#define BSTRIDE 144   /* 128 + 16 */
#define BSTAGE  (128 * BSTRIDE)            /* 18432 */
#define A_BYTES (BM * ASTRIDE)             /* 135168 */
#define SMEM_TOTAL (A_BYTES + 4 * BSTAGE)  /* 208896 */

// scales: x*16, W*1024 -> logits scaled 16384x ; exp(l) = 2^(l_s * log2e/16384)
#define SW_X 16.0f
#define SW_W 1024.0f
#define EPI_SCALE 8.805453862847030e-5f   /* log2(e)/16384 */

// ---------------- scratch ----------------
__device__ __align__(16) uint8_t g_X8[TOKENS * DMODEL];
__device__ __align__(16) uint8_t g_W8[(size_t)VOCAB * DMODEL];
__device__ float g_ts[TOKENS];
__device__ float g_sum[NSPLITS * TOKENS];

// ---------------- ptx helpers ----------------
__device__ __forceinline__ float ex2f(float x) {
    float r; asm("ex2.approx.f32 %0, %1;" : "=f"(r) : "f"(x)); return r;
}
__device__ __forceinline__ uint16_t cvt2_e4m3(float lo, float hi) {
    uint16_t r;
    asm("cvt.rn.satfinite.e4m3x2.f32 %0, %1, %2;" : "=h"(r) : "f"(hi), "f"(lo));
    return r;
}
__device__ __forceinline__ void mma_f8(float d[4], const uint32_t a[4],
                                       uint32_t b0, uint32_t b1) {
    asm volatile(
        "mma.sync.aligned.m16n8k32.row.col.f32.e4m3.e4m3.f32 "
        "{%0,%1,%2,%3},{%4,%5,%6,%7},{%8,%9},{%0,%1,%2,%3};"
        : "+f"(d[0]), "+f"(d[1]), "+f"(d[2]), "+f"(d[3])
        : "r"(a[0]), "r"(a[1]), "r"(a[2]), "r"(a[3]), "r"(b0), "r"(b1));
}
#define LDMX4(r0, r1, r2, r3, addr)                                          \
    asm volatile("ldmatrix.sync.aligned.m8n8.x4.shared.b16 {%0,%1,%2,%3},[%4];" \
                 : "=r"(r0), "=r"(r1), "=r"(r2), "=r"(r3) : "r"(addr))

// ---------------- fp8 conversion ----------------
__global__ void convert_w8(const float* __restrict__ src) {
    size_t i = ((size_t)blockIdx.x * blockDim.x + threadIdx.x) * 16;
    const float4* s = reinterpret_cast<const float4*>(src + i);
    float4 f0 = s[0], f1 = s[1], f2 = s[2], f3 = s[3];
    uint32_t u0 = (uint32_t)cvt2_e4m3(f0.x * SW_W, f0.y * SW_W) |
                  ((uint32_t)cvt2_e4m3(f0.z * SW_W, f0.w * SW_W) << 16);
    uint32_t u1 = (uint32_t)cvt2_e4m3(f1.x * SW_W, f1.y * SW_W) |
                  ((uint32_t)cvt2_e4m3(f1.z * SW_W, f1.w * SW_W) << 16);
    uint32_t u2 = (uint32_t)cvt2_e4m3(f2.x * SW_W, f2.y * SW_W) |
                  ((uint32_t)cvt2_e4m3(f2.z * SW_W, f2.w * SW_W) << 16);
    uint32_t u3 = (uint32_t)cvt2_e4m3(f3.x * SW_W, f3.y * SW_W) |
                  ((uint32_t)cvt2_e4m3(f3.z * SW_W, f3.w * SW_W) << 16);
    *reinterpret_cast<uint4*>(g_W8 + i) = make_uint4(u0, u1, u2, u3);
}
__global__ void convert_x8(const float* __restrict__ src) {
    size_t i = ((size_t)blockIdx.x * blockDim.x + threadIdx.x) * 16;
    const float4* s = reinterpret_cast<const float4*>(src + i);
    float4 f0 = s[0], f1 = s[1], f2 = s[2], f3 = s[3];
    uint32_t u0 = (uint32_t)cvt2_e4m3(f0.x * SW_X, f0.y * SW_X) |
                  ((uint32_t)cvt2_e4m3(f0.z * SW_X, f0.w * SW_X) << 16);
    uint32_t u1 = (uint32_t)cvt2_e4m3(f1.x * SW_X, f1.y * SW_X) |
                  ((uint32_t)cvt2_e4m3(f1.z * SW_X, f1.w * SW_X) << 16);
    uint32_t u2 = (uint32_t)cvt2_e4m3(f2.x * SW_X, f2.y * SW_X) |
                  ((uint32_t)cvt2_e4m3(f2.z * SW_X, f2.w * SW_X) << 16);
    uint32_t u3 = (uint32_t)cvt2_e4m3(f3.x * SW_X, f3.y * SW_X) |
                  ((uint32_t)cvt2_e4m3(f3.z * SW_X, f3.w * SW_X) << 16);
    *reinterpret_cast<uint4*>(g_X8 + i) = make_uint4(u0, u1, u2, u3);
}

// ---------------- target score (exact fp32) ----------------
__global__ void target_score_kernel(const float* __restrict__ x,
                                    const float* __restrict__ w,
                                    const int* __restrict__ target) {
    int t = blockIdx.x * 8 + (threadIdx.x >> 5);
    int lane = threadIdx.x & 31;
    if (t >= TOKENS) return;
    int tgt = target[t];
    const float4* xr = reinterpret_cast<const float4*>(x + (size_t)t * DMODEL);
    const float4* wr = reinterpret_cast<const float4*>(w + (size_t)tgt * DMODEL);
    float s = 0.0f;
    #pragma unroll
    for (int i = lane; i < DMODEL / 4; i += 32) {
        float4 a = xr[i]; float4 b = wr[i];
        s += a.x * b.x + a.y * b.y + a.z * b.z + a.w * b.w;
    }
    #pragma unroll
    for (int o = 16; o; o >>= 1) s += __shfl_xor_sync(0xffffffffu, s, o);
    if (lane == 0) g_ts[t] = s;
}

// B-chunk producer: one (n-tile, k-chunk) = 128 rows x 128 B via cp.async.
// 1024 chunks of 16B over 512 threads -> 2 per thread (rows tid>>3 and 64+tid>>3).
__device__ __forceinline__ void issue_b(int q, const uint8_t* src_base,
                                        uint32_t dst_base) {
    int nt_idx = q >> 2;                     // vocab tile index within split
    int kc = q & 3;
    const uint8_t* src = src_base + (size_t)nt_idx * (NSPLITS * BN * DMODEL) + kc * BK;
    uint32_t dst = dst_base + (uint32_t)((q & 3) * BSTAGE);
    asm volatile("cp.async.cg.shared.global [%0], [%1], 16;\n"
                 :: "r"(dst), "l"(src));
    asm volatile("cp.async.cg.shared.global [%0], [%1], 16;\n"
                 :: "r"(dst + 64 * BSTRIDE), "l"(src + (size_t)64 * DMODEL));
    asm volatile("cp.async.commit_group;\n" ::: "memory");
}

// ---------------- main CE partial kernel (fp8 mma.sync, 512 thr, 16x1 warps) --------
__global__ void __launch_bounds__(512, 1) ce8_kernel() {
    extern __shared__ char smem[];
    const int tid = threadIdx.x;
    const int lane = tid & 31;
    const int wid = tid >> 5;            // warp owns m-rows [wid*16, wid*16+16)
    const int tile_m = blockIdx.x;
    const int split  = blockIdx.y;

    const uint32_t As_u = (uint32_t)__cvta_generic_to_shared(smem);
    const uint32_t Bs_u = As_u + A_BYTES;

    // ---- A tile: 256 x 512 fp8, loaded once ----
    {
        const uint8_t* src = g_X8 + (size_t)tile_m * (BM * DMODEL);
        #pragma unroll
        for (int it = 0; it < 16; ++it) {
            int ch = tid + it * 512;      // 8192 chunks of 16B, 32 per row
            int row = ch >> 5, c16 = ch & 31;
            uint32_t sa = As_u + (uint32_t)(row * ASTRIDE + c16 * 16);
            const void* g = (const void*)(src + (size_t)row * DMODEL + c16 * 16);
            asm volatile("cp.async.cg.shared.global [%0], [%1], 16;\n" :: "r"(sa), "l"(g));
        }
        asm volatile("cp.async.commit_group;\n" ::: "memory");
    }

    const int ntile_cnt = (NTILES_N - 1 - split) / NSPLITS + 1;  // 27 or 28
    const int Q = ntile_cnt * 4;

    // per-thread producer addressing (hoisted)
    const uint8_t* bsrc_base = g_W8 + (size_t)split * (BN * DMODEL)
                             + (size_t)(tid >> 3) * DMODEL + (tid & 7) * 16;
    const uint32_t bdst_base = Bs_u + (uint32_t)((tid >> 3) * BSTRIDE + (tid & 7) * 16);

    issue_b(0, bsrc_base, bdst_base);
    issue_b(1, bsrc_base, bdst_base);
    issue_b(2, bsrc_base, bdst_base);

    float rs0 = 0.0f, rs1 = 0.0f;
    float acc[16][4];                    // 16 n8-groups x 4 regs (m16 x n128)

    // ldmatrix addressing (byte offsets; fp8 = 1 byte)
    const uint32_t a_base = As_u +
        (uint32_t)((wid * 16 + (lane & 15)) * ASTRIDE + ((lane >> 4) & 1) * 16);
    const uint32_t b_lane_off =
        (uint32_t)((((lane >> 4) & 1) * 8 + (lane & 7)) * BSTRIDE + ((lane >> 3) & 1) * 16);

    for (int q = 0; q < Q; ++q) {
        int rem = Q - 1 - q;
        if (rem >= 2)      asm volatile("cp.async.wait_group 2;\n" ::: "memory");
        else if (rem == 1) asm volatile("cp.async.wait_group 1;\n" ::: "memory");
        else               asm volatile("cp.async.wait_group 0;\n" ::: "memory");
        __syncthreads();

        int kc = q & 3;
        if (kc == 0) {
            #pragma unroll
            for (int g = 0; g < 16; ++g)
                #pragma unroll
                for (int j = 0; j < 4; ++j) acc[g][j] = 0.0f;
        }
        const bool fin = (kc == 3);

        const uint32_t bbase = Bs_u + (uint32_t)((q & 3) * BSTAGE) + b_lane_off;
        const uint32_t abase = a_base + (uint32_t)(kc * BK);
        #pragma unroll
        for (int ks = 0; ks < 4; ++ks) {      // four k32 steps per 128B chunk
            uint32_t a[4];
            LDMX4(a[0], a[1], a[2], a[3], abase + (uint32_t)(ks * 32));
            #pragma unroll
            for (int nq = 0; nq < 4; ++nq) {  // 4 x (n32 k32)
                uint32_t b0, b1, b2, b3;
                LDMX4(b0, b1, b2, b3, bbase + (uint32_t)(nq * 32 * BSTRIDE + ks * 32));
                mma_f8(acc[nq * 4 + 0], a, b0, b1);
                mma_f8(acc[nq * 4 + 1], a, b2, b3);
                uint32_t c0, c1, c2, c3;
                LDMX4(c0, c1, c2, c3, bbase + (uint32_t)((nq * 32 + 16) * BSTRIDE + ks * 32));
                mma_f8(acc[nq * 4 + 2], a, c0, c1);
                mma_f8(acc[nq * 4 + 3], a, c2, c3);
                if (ks == 3 && fin) {
                    // this quadrant's accumulators are final: fold exp now so the
                    // MUFU burst overlaps the remaining quadrants' MMA stream
                    #pragma unroll
                    for (int g = nq * 4; g < nq * 4 + 4; ++g) {
                        rs0 += ex2f(acc[g][0] * EPI_SCALE) + ex2f(acc[g][1] * EPI_SCALE);
                        rs1 += ex2f(acc[g][2] * EPI_SCALE) + ex2f(acc[g][3] * EPI_SCALE);
                    }
                }
            }
        }

        if (q + 3 < Q) issue_b(q + 3, bsrc_base, bdst_base);
    }

    // ---- warp-private reduce: sum over the 4 lanes of each quad (n direction) ----
    rs0 += __shfl_xor_sync(0xffffffffu, rs0, 1);
    rs0 += __shfl_xor_sync(0xffffffffu, rs0, 2);
    rs1 += __shfl_xor_sync(0xffffffffu, rs1, 1);
    rs1 += __shfl_xor_sync(0xffffffffu, rs1, 2);
    if ((lane & 3) == 0) {
        int row = tile_m * BM + wid * 16 + (lane >> 2);
        g_sum[split * TOKENS + row] = rs0;
        g_sum[split * TOKENS + row + 8] = rs1;
    }
}

// ---------------- final loss reduce ----------------
__global__ void loss_kernel(float* __restrict__ out) {
    __shared__ float sm[256];
    float acc = 0.0f;
    for (int t = threadIdx.x; t < TOKENS; t += 256) {
        float S = 0.0f;
        #pragma unroll
        for (int s = 0; s < NSPLITS; ++s) S += g_sum[s * TOKENS + t];
        acc += logf(S) - g_ts[t];
    }
    sm[threadIdx.x] = acc;
    __syncthreads();
    #pragma unroll
    for (int o = 128; o; o >>= 1) {
        if (threadIdx.x < o) sm[threadIdx.x] += sm[threadIdx.x + o];
        __syncthreads();
    }
    if (threadIdx.x == 0) out[0] = sm[0];
}

// ---------------- launch ----------------
extern "C" void kernel_launch(void* const* d_in, const int* in_sizes, int n_in,
                              void* d_out, int out_size) {
    const float* x = (const float*)d_in[0];
    const float* w = (const float*)d_in[1];
    const int* target = (const int*)d_in[2];
    float* out = (float*)d_out;
    (void)in_sizes; (void)n_in; (void)out_size;

    cudaFuncSetAttribute(ce8_kernel, cudaFuncAttributeMaxDynamicSharedMemorySize,
                         SMEM_TOTAL);

    convert_w8<<<16000, 256>>>(w);                    // 16000*256*16 = 65,536,000
    convert_x8<<<512, 256>>>(x);                      // 512*256*16  =  2,097,152
    target_score_kernel<<<TOKENS / 8, 256>>>(x, w, target);
    ce8_kernel<<<dim3(MTILES, NSPLITS), 512, SMEM_TOTAL>>>();
    loss_kernel<<<1, 256>>>(out);
}